// round 4
// baseline (speedup 1.0000x reference)
#include <cuda_runtime.h>
#include <math.h>

// GridPostProcessor (R=50000), fused single kernel:
//   grid_logits: (R, 9, 28, 28) f32 -> per (r,c) max+argmax over 784
//   det_bboxes : (R, 4) f32
//   out        : (R, 4) f32
// One block per row: 9 warps, warp c scans channel c (6 unconditional +
// 1 predicated float4 loads per lane, 4 independent compare chains),
// warp-shuffle reduce, epilogue parallelized across warp 0.
// launch_bounds(288, 6): cap regs at 37 so 6 blocks fit per SM (288*37*6 = 63936).

#define HALF 28
#define HW   (HALF * HALF)     // 784
#define CH   9

__global__ __launch_bounds__(288, 6) void grid_post_fused(
    const float* __restrict__ logits,
    const float* __restrict__ bboxes,
    float* __restrict__ out,
    int R)
{
    const int r    = blockIdx.x;
    const int warp = threadIdx.x >> 5;   // channel
    const int lane = threadIdx.x & 31;

    __shared__ float2 s_mi[CH];                 // (max, idx-as-float)
    __shared__ float  s_sc[CH], s_ax[CH], s_ay[CH];
    __shared__ float4 s_bb;

    // ---- per-warp channel scan (streaming loads, read-once) ----
    const float4* __restrict__ base =
        (const float4*)(logits + ((size_t)r * CH + warp) * HW);

    float4 v[7];
#pragma unroll
    for (int k = 0; k < 6; k++) v[k] = __ldcs(&base[lane + 32 * k]);
    v[6] = make_float4(-INFINITY, -INFINITY, -INFINITY, -INFINITY);
    if (lane < 4) v[6] = __ldcs(&base[192 + lane]);

    // 4 independent compare-select chains (idx ascending within a chain,
    // strict '>' keeps first occurrence).
    float bx = v[0].x, by = v[0].y, bz = v[0].z, bw = v[0].w;
    int   ix = 0,      iy = 0,      iz = 0,      iw = 0;
#pragma unroll
    for (int k = 1; k < 7; k++) {
        if (v[k].x > bx) { bx = v[k].x; ix = k; }
        if (v[k].y > by) { by = v[k].y; iy = k; }
        if (v[k].z > bz) { bz = v[k].z; iz = k; }
        if (v[k].w > bw) { bw = v[k].w; iw = k; }
    }
    auto vec_of = [&](int k) { return (k < 6) ? (lane + 32 * k) : (192 + lane); };
    int ex = 4 * vec_of(ix) + 0;
    int ey = 4 * vec_of(iy) + 1;
    int ez = 4 * vec_of(iz) + 2;
    int ew = 4 * vec_of(iw) + 3;

    float best = bx; int bidx = ex;
    if (by > best || (by == best && ey < bidx)) { best = by; bidx = ey; }
    if (bz > best || (bz == best && ez < bidx)) { best = bz; bidx = ez; }
    if (bw > best || (bw == best && ew < bidx)) { best = bw; bidx = ew; }

#pragma unroll
    for (int off = 16; off > 0; off >>= 1) {
        float ov = __shfl_down_sync(0xffffffffu, best, off);
        int   oi = __shfl_down_sync(0xffffffffu, bidx, off);
        if (ov > best || (ov == best && oi < bidx)) { best = ov; bidx = oi; }
    }
    if (lane == 0) s_mi[warp] = make_float2(best, __int_as_float(bidx));

    // Prefetch bboxes into smem from warp 0 BEFORE the barrier: its latency
    // overlaps the other warps draining into __syncthreads.
    if (warp == 0 && lane == 0) s_bb = __ldg(&((const float4*)bboxes)[r]);
    __syncthreads();

    // ---- epilogue: warp 0 only ----
    if (warp == 0) {
        // sub-region offsets (GRID_SIZE=3, WHOLE_MAP=56): 0, 14, 28
        const int sub_x[CH] = {0, 14, 28, 0, 14, 28, 0, 14, 28};
        const int sub_y[CH] = {0, 0, 0, 14, 14, 14, 28, 28, 28};

        const float4 bb = s_bb;
        const float width  = bb.z - bb.x;
        const float height = bb.w - bb.y;
        const float x1 = bb.x - 0.5f * width;    // MAPPING_RATIO = 1
        const float y1 = bb.y - 0.5f * height;
        const float wk = width  * (1.0f / 28.0f);
        const float hk = height * (1.0f / 28.0f);

        if (lane < CH) {
            float2 mi = s_mi[lane];
            int id = __float_as_int(mi.y);
            s_sc[lane] = 1.0f / (1.0f + __expf(-mi.x));
            int xs = (id % HALF) + sub_x[lane];
            int ys = (id / HALF) + sub_y[lane];
            s_ax[lane] = ((float)xs + 0.5f) * wk + x1;
            s_ay[lane] = ((float)ys + 0.5f) * hk + y1;
        }
        __syncwarp();

        if (lane < 4) {
            // edge channel triplets:
            //   out0 (bx1): x over {0,1,2}; out1 (by1): y over {0,3,6}
            //   out2 (bx2): x over {6,7,8}; out3 (by2): y over {2,5,8}
            const int e0[4] = {0, 0, 6, 2};
            const int e1[4] = {1, 3, 7, 5};
            const int e2[4] = {2, 6, 8, 8};
            int c0 = e0[lane], c1 = e1[lane], c2 = e2[lane];
            const float* coord = (lane & 1) ? s_ay : s_ax;
            float num = coord[c0] * s_sc[c0] + coord[c1] * s_sc[c1] + coord[c2] * s_sc[c2];
            float den = s_sc[c0] + s_sc[c1] + s_sc[c2];
            out[r * 4 + lane] = num / den;
        }
    }
}

extern "C" void kernel_launch(void* const* d_in, const int* in_sizes, int n_in,
                              void* d_out, int out_size) {
    const float* logits = (const float*)d_in[0];   // (R, 9, 28, 28)
    const float* bboxes = (const float*)d_in[1];   // (R, 4)
    float* out = (float*)d_out;                    // (R, 4)

    int R = in_sizes[0] / (CH * HW);               // 50000

    grid_post_fused<<<R, 288>>>(logits, bboxes, out, R);
}

// round 8
// speedup vs baseline: 1.1431x; 1.1431x over previous
#include <cuda_runtime.h>
#include <math.h>

// GridPostProcessor (R=50000), fused single kernel:
//   grid_logits: (R, 9, 28, 28) f32 -> per (r,c) max+argmax over 784
//   det_bboxes : (R, 4) f32
//   out        : (R, 4) f32
// One block per row, 9 warps = 9 channels. Per lane: 6 unconditional +
// 1 predicated float4 loads, value-only FMNMX max tree + shfl_xor reduce,
// then equality re-scan on in-register values for the first-occurrence index
// (pred-as-data SEL/IMNMX, no guard-predicate chains).

#define HALF 28
#define HW   (HALF * HALF)     // 784
#define CH   9

__global__ __launch_bounds__(288) void grid_post_fused(
    const float* __restrict__ logits,
    const float* __restrict__ bboxes,
    float* __restrict__ out,
    int R)
{
    const int r    = blockIdx.x;
    const int warp = threadIdx.x >> 5;   // channel
    const int lane = threadIdx.x & 31;

    __shared__ float2 s_mi[CH];          // (max, idx-as-float)
    __shared__ float  s_sc[CH], s_ax[CH], s_ay[CH];
    __shared__ float4 s_bb;

    // ---- loads: streaming, fully unrolled, front-batched ----
    const float4* __restrict__ base =
        (const float4*)(logits + ((size_t)r * CH + warp) * HW);

    float4 v[7];
#pragma unroll
    for (int k = 0; k < 6; k++) v[k] = __ldcs(&base[lane + 32 * k]);
    v[6] = make_float4(-INFINITY, -INFINITY, -INFINITY, -INFINITY);
    if (lane < 4) v[6] = __ldcs(&base[192 + lane]);

    // ---- phase 1: value-only max (FMNMX tree, lat-4 data path) ----
    float pm[7];
#pragma unroll
    for (int k = 0; k < 7; k++)
        pm[k] = fmaxf(fmaxf(v[k].x, v[k].y), fmaxf(v[k].z, v[k].w));
    float m = fmaxf(fmaxf(fmaxf(pm[0], pm[1]), fmaxf(pm[2], pm[3])),
                    fmaxf(fmaxf(pm[4], pm[5]), pm[6]));
#pragma unroll
    for (int off = 16; off > 0; off >>= 1)
        m = fmaxf(m, __shfl_xor_sync(0xffffffffu, m, off));
    // every lane now holds the channel-wide max m

    // ---- phase 2: first-occurrence index of m (pred-as-data select/min) ----
    int loc = 0x7FFFFFFF;
#pragma unroll
    for (int k = 0; k < 7; k++) {
        int vec = (k < 6) ? (lane + 32 * k) : (192 + lane);
        int e   = vec << 2;
        int cx = (v[k].x == m) ? (e + 0) : 0x7FFFFFFF;
        int cy = (v[k].y == m) ? (e + 1) : 0x7FFFFFFF;
        int cz = (v[k].z == m) ? (e + 2) : 0x7FFFFFFF;
        int cw = (v[k].w == m) ? (e + 3) : 0x7FFFFFFF;
        loc = min(loc, min(min(cx, cy), min(cz, cw)));
    }
#pragma unroll
    for (int off = 16; off > 0; off >>= 1)
        loc = min(loc, __shfl_xor_sync(0xffffffffu, loc, off));

    if (lane == 0) s_mi[warp] = make_float2(m, __int_as_float(loc));

    // Prefetch bboxes before the barrier: latency overlaps warp drain.
    if (warp == 0 && lane == 0) s_bb = __ldg(&((const float4*)bboxes)[r]);
    __syncthreads();

    // ---- epilogue: warp 0 only ----
    if (warp == 0) {
        // sub-region offsets (GRID_SIZE=3, WHOLE_MAP=56): 0, 14, 28
        const int sub_x[CH] = {0, 14, 28, 0, 14, 28, 0, 14, 28};
        const int sub_y[CH] = {0, 0, 0, 14, 14, 14, 28, 28, 28};

        const float4 bb = s_bb;
        const float width  = bb.z - bb.x;
        const float height = bb.w - bb.y;
        const float x1 = bb.x - 0.5f * width;    // MAPPING_RATIO = 1
        const float y1 = bb.y - 0.5f * height;
        const float wk = width  * (1.0f / 28.0f);
        const float hk = height * (1.0f / 28.0f);

        if (lane < CH) {
            float2 mi = s_mi[lane];
            int id = __float_as_int(mi.y);
            s_sc[lane] = 1.0f / (1.0f + __expf(-mi.x));
            int xs = (id % HALF) + sub_x[lane];
            int ys = (id / HALF) + sub_y[lane];
            s_ax[lane] = ((float)xs + 0.5f) * wk + x1;
            s_ay[lane] = ((float)ys + 0.5f) * hk + y1;
        }
        __syncwarp();

        if (lane < 4) {
            // out0 (bx1): x over {0,1,2}; out1 (by1): y over {0,3,6}
            // out2 (bx2): x over {6,7,8}; out3 (by2): y over {2,5,8}
            const int e0[4] = {0, 0, 6, 2};
            const int e1[4] = {1, 3, 7, 5};
            const int e2[4] = {2, 6, 8, 8};
            int c0 = e0[lane], c1 = e1[lane], c2 = e2[lane];
            const float* coord = (lane & 1) ? s_ay : s_ax;
            float num = coord[c0] * s_sc[c0] + coord[c1] * s_sc[c1] + coord[c2] * s_sc[c2];
            float den = s_sc[c0] + s_sc[c1] + s_sc[c2];
            out[r * 4 + lane] = num / den;
        }
    }
}

extern "C" void kernel_launch(void* const* d_in, const int* in_sizes, int n_in,
                              void* d_out, int out_size) {
    const float* logits = (const float*)d_in[0];   // (R, 9, 28, 28)
    const float* bboxes = (const float*)d_in[1];   // (R, 4)
    float* out = (float*)d_out;                    // (R, 4)

    int R = in_sizes[0] / (CH * HW);               // 50000

    grid_post_fused<<<R, 288>>>(logits, bboxes, out, R);
}